// round 1
// baseline (speedup 1.0000x reference)
#include <cuda_runtime.h>
#include <math.h>
#include <stdint.h>

// Problem dims
#define Bn   4096
#define Hd   512
#define Fd   256
#define Zd   64
#define Td   16
#define INd  832      // Z + H + F
#define Gd   2048     // 4H
#define XLD  832      // X state row stride: [z(64) | y(256) | h(512)]

// ---------------- persistent scratch (static device allocations) ----------------
__device__ float g_Wcat [INd * Gd];      // permuted [Wx_z ; Wx_y ; Wh]  (832 x 2048)
__device__ float g_W4cat[1024 * Zd];     // [W4_s ; W4_yj ; W4_yprev]    (1024 x 64)
__device__ float g_W7cat[768 * Zd];      // [W7_s ; W7_yprev]            (768 x 64)
__device__ float g_baseg[(size_t)Bn * Gd];   // h_i @ Wx_h + b_lstm
__device__ float g_base4[Bn * Zd];           // h_i @ W4_h + b4
__device__ float g_base7[Bn * Zd];           // h_i @ W7_h + b7
__device__ float g_gates[(size_t)Bn * Gd];
__device__ float g_X    [(size_t)Bn * XLD];  // [z | y_prev | h]
__device__ float g_c    [Bn * Hd];
__device__ float g_y    [Bn * Fd];
__device__ float g_t1   [Bn * Fd];
__device__ float g_t2   [Bn * Fd];
__device__ float g_infin[(size_t)Bn * 1024]; // [c | y_j | y_prev]
__device__ float g_priin[(size_t)Bn * 768];  // [c | y_prev]
__device__ float g_hz   [Bn * Zd];
__device__ float g_mean [Bn * Zd];
__device__ float g_lv   [Bn * Zd];
__device__ float g_hzp  [Bn * Zd];
__device__ float g_meanp[Bn * Zd];
__device__ float g_lvp  [Bn * Zd];

// ---------------- generic register-blocked SGEMM ----------------
// C[M,N] = op( A[M,K](lda) @ Bw[K,N](ldb) + init ), init: 0=none,1=bias row,2=full matrix
template<int BM,int BN,int BK,int TM,int TN,int NT,bool RELU,int CI>
__global__ void __launch_bounds__(NT) sgemm(
    const float* __restrict__ A, int lda,
    const float* __restrict__ Bw, int ldb,
    const float* __restrict__ Ci, int ldci,
    float* __restrict__ C, int ldc,
    int K)
{
    __shared__ float As[BK][BM];
    __shared__ float Bs[BK][BN];
    const int bm = blockIdx.y * BM;
    const int bn = blockIdx.x * BN;
    const int tid = threadIdx.x;
    const int tx = tid % (BN / TN);
    const int ty = tid / (BN / TN);

    float acc[TM][TN];
#pragma unroll
    for (int i = 0; i < TM; i++)
#pragma unroll
        for (int j = 0; j < TN; j++) acc[i][j] = 0.f;

    constexpr int AV = BM * BK / (4 * NT);   // float4 loads per thread (A)
    constexpr int BV = BK * BN / (4 * NT);   // float4 loads per thread (B)
    static_assert(AV >= 1 && BV >= 1, "tile too small");

    for (int k0 = 0; k0 < K; k0 += BK) {
#pragma unroll
        for (int i = 0; i < AV; i++) {
            int idx = tid + i * NT;                // each idx covers 4 consecutive k
            int row = idx / (BK / 4);
            int kc  = (idx % (BK / 4)) * 4;
            float4 v = *(const float4*)&A[(size_t)(bm + row) * lda + k0 + kc];
            As[kc + 0][row] = v.x; As[kc + 1][row] = v.y;
            As[kc + 2][row] = v.z; As[kc + 3][row] = v.w;
        }
#pragma unroll
        for (int i = 0; i < BV; i++) {
            int idx = (tid + i * NT) * 4;
            int row = idx / BN;
            int col = idx % BN;
            *(float4*)&Bs[row][col] =
                *(const float4*)&Bw[(size_t)(k0 + row) * ldb + bn + col];
        }
        __syncthreads();
#pragma unroll
        for (int k = 0; k < BK; k++) {
            float a[TM], b[TN];
#pragma unroll
            for (int i = 0; i < TM; i++) a[i] = As[k][ty * TM + i];
#pragma unroll
            for (int j = 0; j < TN; j++) b[j] = Bs[k][tx * TN + j];
#pragma unroll
            for (int i = 0; i < TM; i++)
#pragma unroll
                for (int j = 0; j < TN; j++) acc[i][j] += a[i] * b[j];
        }
        __syncthreads();
    }

#pragma unroll
    for (int i = 0; i < TM; i++) {
        int r = bm + ty * TM + i;
#pragma unroll
        for (int j = 0; j < TN; j++) {
            int cc = bn + tx * TN + j;
            float v = acc[i][j];
            if (CI == 1) v += Ci[cc];
            else if (CI == 2) v += Ci[(size_t)r * ldci + cc];
            if (RELU) v = fmaxf(v, 0.f);
            C[(size_t)r * ldc + cc] = v;
        }
    }
}

// ---------------- pointwise kernels ----------------
__global__ void zero_state() {
    size_t n = (size_t)Bn * XLD + (size_t)Bn * Hd;
    size_t i = (size_t)blockIdx.x * blockDim.x + threadIdx.x;
    if (i >= n) return;
    if (i < (size_t)Bn * XLD) g_X[i] = 0.f;
    else g_c[i - (size_t)Bn * XLD] = 0.f;
}

__global__ void prep_weights(const float* __restrict__ Wx, const float* __restrict__ Wh,
                             const float* __restrict__ W4, const float* __restrict__ W7) {
    size_t i = (size_t)blockIdx.x * blockDim.x + threadIdx.x;
    const size_t n1 = (size_t)INd * Gd, n2 = n1 + 1024 * Zd, n3 = n2 + 768 * Zd;
    if (i < n1) {
        int r = (int)(i / Gd), c = (int)(i % Gd);
        float v;
        if (r < 64)        v = Wx[(size_t)r * Gd + c];                 // z rows 0..63
        else if (r < 320)  v = Wx[(size_t)(576 + r - 64) * Gd + c];    // y rows 576..831
        else               v = Wh[(size_t)(r - 320) * Gd + c];         // h rows
        g_Wcat[i] = v;
    } else if (i < n2) {
        size_t k = i - n1; int r = (int)(k / Zd), c = (int)(k % Zd);
        float v;
        if (r < 512)       v = W4[(size_t)(512 + r) * Zd + c];         // s_j
        else if (r < 768)  v = W4[(size_t)(1024 + r - 512) * Zd + c];  // y_j
        else               v = W4[(size_t)(1280 + r - 768) * Zd + c];  // y_prev
        g_W4cat[k] = v;
    } else if (i < n3) {
        size_t k = i - n2; int r = (int)(k / Zd), c = (int)(k % Zd);
        float v = (r < 512) ? W7[(size_t)(512 + r) * Zd + c]
                            : W7[(size_t)(1024 + r - 512) * Zd + c];
        g_W7cat[k] = v;
    }
}

__global__ void lstm_pw() {
    int idx = blockIdx.x * blockDim.x + threadIdx.x;
    if (idx >= Bn * Hd) return;
    int b = idx / Hd, j = idx % Hd;
    const float* g = &g_gates[(size_t)b * Gd];
    float ig = g[j], fg = g[j + Hd], gg = g[j + 2 * Hd], og = g[j + 3 * Hd];
    float si = 1.f / (1.f + expf(-ig));
    float sf = 1.f / (1.f + expf(-fg));
    float so = 1.f / (1.f + expf(-og));
    float cn = sf * g_c[idx] + si * tanhf(gg);
    float hn = so * tanhf(cn);
    g_c[idx] = cn;
    g_X[(size_t)b * XLD + 320 + j] = hn;   // h slice
}

// pack inf/prior inputs, commit y_j into state, emit fake_input[:,t,:]
__global__ void pack_pw(int t, float* __restrict__ out_fake) {
    int idx = blockIdx.x * blockDim.x + threadIdx.x;
    if (idx >= Bn * (Hd + Fd)) return;
    int b = idx / (Hd + Fd), c = idx % (Hd + Fd);
    if (c < Hd) {
        float v = g_c[b * Hd + c];
        g_infin[(size_t)b * 1024 + c] = v;
        g_priin[(size_t)b * 768 + c]  = v;
    } else {
        int f = c - Hd;
        float yv = g_y[b * Fd + f];
        float yp = g_X[(size_t)b * XLD + 64 + f];
        g_infin[(size_t)b * 1024 + 512 + f] = yv;
        g_infin[(size_t)b * 1024 + 768 + f] = yp;
        g_priin[(size_t)b * 768 + 512 + f]  = yp;
        g_X[(size_t)b * XLD + 64 + f] = yv;   // y_prev <- y_j for next step
        out_fake[(size_t)b * Td * Fd + (size_t)t * Fd + f] = yv;
    }
}

__global__ void zinf_pw(int t, const float* __restrict__ eps,
                        float* __restrict__ out_mean, float* __restrict__ out_lv,
                        float* __restrict__ out_z) {
    int idx = blockIdx.x * blockDim.x + threadIdx.x;
    if (idx >= Bn * Zd) return;
    int b = idx / Zd, z = idx % Zd;
    float m = g_mean[idx], lv = g_lv[idx];
    float e = eps[(size_t)t * Bn * Zd + idx];
    float zz = m + e * sqrtf(expf(lv));
    out_mean[(size_t)b * Td * Zd + (size_t)t * Zd + z] = m;
    out_lv  [(size_t)b * Td * Zd + (size_t)t * Zd + z] = lv;
    out_z[(size_t)(2 * t) * Bn * Zd + idx] = zz;
    g_X[(size_t)b * XLD + z] = zz;            // z slice for next step
}

__global__ void zpri_pw(int t, const float* __restrict__ eps, float* __restrict__ out_z) {
    int idx = blockIdx.x * blockDim.x + threadIdx.x;
    if (idx >= Bn * Zd) return;
    float zz = g_meanp[idx] + eps[(size_t)t * Bn * Zd + idx] * sqrtf(expf(g_lvp[idx]));
    out_z[(size_t)(2 * t + 1) * Bn * Zd + idx] = zz;
}

// ---------------- host launch ----------------
static float* sym(const void* s) { void* p = nullptr; cudaGetSymbolAddress(&p, s); return (float*)p; }

extern "C" void kernel_launch(void* const* d_in, const int* in_sizes, int n_in,
                              void* d_out, int out_size) {
    const float* h_i     = (const float*)d_in[0];
    const float* eps_inf = (const float*)d_in[1];
    const float* eps_pri = (const float*)d_in[2];
    const float* Wx      = (const float*)d_in[3];
    const float* Wh      = (const float*)d_in[4];
    const float* b_lstm  = (const float*)d_in[5];
    const float* W1 = (const float*)d_in[6],  *b1 = (const float*)d_in[7];
    const float* W2 = (const float*)d_in[8],  *b2 = (const float*)d_in[9];
    const float* W3 = (const float*)d_in[10], *b3 = (const float*)d_in[11];
    const float* W4 = (const float*)d_in[12], *b4 = (const float*)d_in[13];
    const float* W5 = (const float*)d_in[14], *b5 = (const float*)d_in[15];
    const float* W6 = (const float*)d_in[16], *b6 = (const float*)d_in[17];
    const float* W7 = (const float*)d_in[18], *b7 = (const float*)d_in[19];
    const float* W8 = (const float*)d_in[20], *b8 = (const float*)d_in[21];
    const float* W9 = (const float*)d_in[22], *b9 = (const float*)d_in[23];

    float* out      = (float*)d_out;
    float* out_fake = out;                                    // [B,T,F]
    float* out_mean = out_fake + (size_t)Bn * Td * Fd;        // [B,T,Z]
    float* out_lv   = out_mean + (size_t)Bn * Td * Zd;        // [B,T,Z]
    float* out_z    = out_lv   + (size_t)Bn * Td * Zd;        // [T,2,B,Z]

    float* pWcat  = sym(g_Wcat);  float* pW4cat = sym(g_W4cat); float* pW7cat = sym(g_W7cat);
    float* pBaseg = sym(g_baseg); float* pBase4 = sym(g_base4); float* pBase7 = sym(g_base7);
    float* pGates = sym(g_gates); float* pX     = sym(g_X);     float* pC     = sym(g_c);
    float* pY     = sym(g_y);     float* pT1    = sym(g_t1);    float* pT2    = sym(g_t2);
    float* pInf   = sym(g_infin); float* pPri   = sym(g_priin);
    float* pHz    = sym(g_hz);    float* pMean  = sym(g_mean);  float* pLv    = sym(g_lv);
    float* pHzp   = sym(g_hzp);   float* pMeanp = sym(g_meanp); float* pLvp   = sym(g_lvp);

    // init
    {
        size_t n = (size_t)Bn * XLD + (size_t)Bn * Hd;
        zero_state<<<(unsigned)((n + 255) / 256), 256>>>();
        size_t m = (size_t)INd * Gd + 1024 * Zd + 768 * Zd;
        prep_weights<<<(unsigned)((m + 255) / 256), 256>>>(Wx, Wh, W4, W7);
    }

    // hoisted (time-invariant) GEMMs
    sgemm<128,128,16,8,8,256,false,1><<<dim3(Gd/128, Bn/128), 256>>>(
        h_i, Hd, Wx + (size_t)64 * Gd, Gd, b_lstm, 0, pBaseg, Gd, Hd);
    sgemm<32,64,16,4,4,128,false,1><<<dim3(1, Bn/32), 128>>>(
        h_i, Hd, W4, Zd, b4, 0, pBase4, Zd, Hd);
    sgemm<32,64,16,4,4,128,false,1><<<dim3(1, Bn/32), 128>>>(
        h_i, Hd, W7, Zd, b7, 0, pBase7, Zd, Hd);

    for (int t = 0; t < Td; t++) {
        // gates = base_g + [z|y_prev|h] @ Wcat        (M=4096,N=2048,K=832)
        sgemm<128,128,16,8,8,256,false,2><<<dim3(Gd/128, Bn/128), 256>>>(
            pX, XLD, pWcat, Gd, pBaseg, Gd, pGates, Gd, INd);
        lstm_pw<<<(Bn * Hd + 255) / 256, 256>>>();

        // decoder MLP: y = relu(relu(relu(h@W1+b1)@W2+b2)@W3+b3)
        sgemm<64,64,16,4,4,256,true,1><<<dim3(Fd/64, Bn/64), 256>>>(
            pX + 320, XLD, W1, Fd, b1, 0, pT1, Fd, Hd);
        sgemm<64,64,16,4,4,256,true,1><<<dim3(Fd/64, Bn/64), 256>>>(
            pT1, Fd, W2, Fd, b2, 0, pT2, Fd, Fd);
        sgemm<64,64,16,4,4,256,true,1><<<dim3(Fd/64, Bn/64), 256>>>(
            pT2, Fd, W3, Fd, b3, 0, pY, Fd, Fd);

        pack_pw<<<(Bn * (Hd + Fd) + 255) / 256, 256>>>(t, out_fake);

        // inference head
        sgemm<32,64,16,4,4,128,true,2><<<dim3(1, Bn/32), 128>>>(
            pInf, 1024, pW4cat, Zd, pBase4, Zd, pHz, Zd, 1024);
        sgemm<32,64,16,4,4,128,true,1><<<dim3(1, Bn/32), 128>>>(
            pHz, Zd, W5, Zd, b5, 0, pMean, Zd, Zd);
        sgemm<32,64,16,4,4,128,true,1><<<dim3(1, Bn/32), 128>>>(
            pHz, Zd, W6, Zd, b6, 0, pLv, Zd, Zd);
        zinf_pw<<<(Bn * Zd + 255) / 256, 256>>>(t, eps_inf, out_mean, out_lv, out_z);

        // prior head
        sgemm<32,64,16,4,4,128,true,2><<<dim3(1, Bn/32), 128>>>(
            pPri, 768, pW7cat, Zd, pBase7, Zd, pHzp, Zd, 768);
        sgemm<32,64,16,4,4,128,true,1><<<dim3(1, Bn/32), 128>>>(
            pHzp, Zd, W8, Zd, b8, 0, pMeanp, Zd, Zd);
        sgemm<32,64,16,4,4,128,true,1><<<dim3(1, Bn/32), 128>>>(
            pHzp, Zd, W9, Zd, b9, 0, pLvp, Zd, Zd);
        zpri_pw<<<(Bn * Zd + 255) / 256, 256>>>(t, eps_pri, out_z);
    }
}

// round 2
// speedup vs baseline: 1.5428x; 1.5428x over previous
#include <cuda_runtime.h>
#include <cuda_bf16.h>
#include <math.h>
#include <stdint.h>

// Problem dims
#define Bn   4096
#define Hd   512
#define Fd   256
#define Zd   64
#define Td   16
#define INd  832      // Z + H + F
#define Gd   2048     // 4H
#define XLD  832      // X state row stride: [z(64) | y(256) | h(512)]

// ---------------- persistent scratch ----------------
__device__ float g_baseg[(size_t)Bn * Gd];
__device__ float g_base4[Bn * Zd];
__device__ float g_base7[Bn * Zd];
__device__ float g_gates[(size_t)Bn * Gd];
__device__ float g_X    [(size_t)Bn * XLD];  // [z | y_prev | h]
__device__ float g_c    [Bn * Hd];
__device__ float g_y    [Bn * Fd];
__device__ float g_t1   [Bn * Fd];
__device__ float g_t2   [Bn * Fd];
__device__ float g_infin[(size_t)Bn * 1024]; // [c | y_j | y_prev]
__device__ float g_priin[(size_t)Bn * 768];  // [c | y_prev]
__device__ float g_hz   [Bn * Zd];
__device__ float g_hzp  [Bn * Zd];

// bf16 hi/lo pre-split, pre-transposed weights (n-major: W[n][k])
__device__ __nv_bfloat16 g_WcatT_h[(size_t)Gd * INd], g_WcatT_l[(size_t)Gd * INd]; // [2048][832]
__device__ __nv_bfloat16 g_WxhT_h [(size_t)Gd * Hd],  g_WxhT_l [(size_t)Gd * Hd];  // [2048][512]
__device__ __nv_bfloat16 g_W1T_h  [Fd * Hd],  g_W1T_l  [Fd * Hd];   // [256][512]
__device__ __nv_bfloat16 g_W2T_h  [Fd * Fd],  g_W2T_l  [Fd * Fd];   // [256][256]
__device__ __nv_bfloat16 g_W3T_h  [Fd * Fd],  g_W3T_l  [Fd * Fd];
__device__ __nv_bfloat16 g_W4T_h  [Zd * 1024], g_W4T_l [Zd * 1024]; // [64][1024]
__device__ __nv_bfloat16 g_W7T_h  [Zd * 768],  g_W7T_l [Zd * 768];  // [64][768]
__device__ __nv_bfloat16 g_W4bT_h [Zd * Hd],   g_W4bT_l[Zd * Hd];   // [64][512]
__device__ __nv_bfloat16 g_W7bT_h [Zd * Hd],   g_W7bT_l[Zd * Hd];

// ---------------- helpers ----------------
__device__ __forceinline__ void bsplit(float v, __nv_bfloat16& h, __nv_bfloat16& l) {
    h = __float2bfloat16_rn(v);
    l = __float2bfloat16_rn(v - __bfloat162float(h));
}
__device__ __forceinline__ uint32_t bpack(__nv_bfloat16 a, __nv_bfloat16 b) {
    __nv_bfloat162 t; t.x = a; t.y = b;
    return reinterpret_cast<uint32_t&>(t);
}
__device__ __forceinline__ void mma16816(float* c, const uint32_t* a, const uint32_t* b) {
    asm volatile(
        "mma.sync.aligned.m16n8k16.row.col.f32.bf16.bf16.f32 "
        "{%0,%1,%2,%3}, {%4,%5,%6,%7}, {%8,%9}, {%0,%1,%2,%3};\n"
        : "+f"(c[0]), "+f"(c[1]), "+f"(c[2]), "+f"(c[3])
        : "r"(a[0]), "r"(a[1]), "r"(a[2]), "r"(a[3]), "r"(b[0]), "r"(b[1]));
}

// ---------------- tensor-core GEMM (bf16 hi/lo x3 passes, fp32 accum) ----------------
// C[M,N] = op( A[M,K] @ B^T  + init ), B given as n-major bf16 hi/lo [N][K]
// CI: 0=none, 1=bias row Ci[N], 2=matrix Ci[M,N]
template<int BM, int BN, int WM, int WN, int NTH, bool RELU, int CI>
__global__ void __launch_bounds__(NTH) mmagemm(
    const float* __restrict__ A, int lda,
    const __nv_bfloat16* __restrict__ Bh, const __nv_bfloat16* __restrict__ Bl,
    const float* __restrict__ Ci, int ldci,
    float* __restrict__ C, int ldc, int K)
{
    constexpr int KP  = 20;          // padded k-pair stride (16 pairs + 4)
    constexpr int MT  = WM / 16;
    constexpr int NTL = WN / 8;
    constexpr int NWN = BN / WN;

    __shared__ uint32_t As_h[BM * KP], As_l[BM * KP];
    __shared__ uint32_t Bs_h[BN * KP], Bs_l[BN * KP];

    const int tid  = threadIdx.x;
    const int warp = tid >> 5, lane = tid & 31;
    const int g    = lane >> 2, tg = lane & 3;
    const int wm   = (warp / NWN) * WM, wn = (warp % NWN) * WN;
    const int bm   = blockIdx.y * BM,  bn = blockIdx.x * BN;

    float acc[MT][NTL][4];
#pragma unroll
    for (int i = 0; i < MT; i++)
#pragma unroll
        for (int j = 0; j < NTL; j++)
#pragma unroll
            for (int q = 0; q < 4; q++) acc[i][j][q] = 0.f;

    for (int k0 = 0; k0 < K; k0 += 32) {
        // ---- A tile: fp32 -> hi/lo bf16 pairs ----
#pragma unroll
        for (int i = 0; i < BM * 8 / NTH; i++) {
            int idx = tid + i * NTH;
            int row = idx >> 3, kc = (idx & 7) << 2;
            float4 v = *(const float4*)(A + (size_t)(bm + row) * lda + k0 + kc);
            __nv_bfloat16 hx, hy, hz2, hw, lx, ly, lz2, lw;
            bsplit(v.x, hx, lx); bsplit(v.y, hy, ly);
            bsplit(v.z, hz2, lz2); bsplit(v.w, hw, lw);
            int o = row * KP + (kc >> 1);
            *(uint2*)&As_h[o] = make_uint2(bpack(hx, hy), bpack(hz2, hw));
            *(uint2*)&As_l[o] = make_uint2(bpack(lx, ly), bpack(lz2, lw));
        }
        // ---- B tile: pre-split bf16, n-major ----
#pragma unroll
        for (int i = 0; i < BN * 4 / NTH; i++) {
            int idx = tid + i * NTH;
            int row = idx >> 2, seg = idx & 3;
            size_t go = (size_t)(bn + row) * K + k0 + seg * 8;
            uint4 vh = *(const uint4*)(Bh + go);
            uint4 vl = *(const uint4*)(Bl + go);
            int o = row * KP + seg * 4;
            *(uint4*)&Bs_h[o] = vh;
            *(uint4*)&Bs_l[o] = vl;
        }
        __syncthreads();

#pragma unroll
        for (int kkp = 0; kkp < 16; kkp += 8) {
            uint32_t ah[MT][4], al[MT][4], bh[NTL][2], bl[NTL][2];
#pragma unroll
            for (int mt = 0; mt < MT; mt++) {
                int r = wm + mt * 16 + g;
                ah[mt][0] = As_h[r * KP + kkp + tg];
                ah[mt][1] = As_h[(r + 8) * KP + kkp + tg];
                ah[mt][2] = As_h[r * KP + kkp + tg + 4];
                ah[mt][3] = As_h[(r + 8) * KP + kkp + tg + 4];
                al[mt][0] = As_l[r * KP + kkp + tg];
                al[mt][1] = As_l[(r + 8) * KP + kkp + tg];
                al[mt][2] = As_l[r * KP + kkp + tg + 4];
                al[mt][3] = As_l[(r + 8) * KP + kkp + tg + 4];
            }
#pragma unroll
            for (int nt = 0; nt < NTL; nt++) {
                int r = wn + nt * 8 + g;
                bh[nt][0] = Bs_h[r * KP + kkp + tg];
                bh[nt][1] = Bs_h[r * KP + kkp + tg + 4];
                bl[nt][0] = Bs_l[r * KP + kkp + tg];
                bl[nt][1] = Bs_l[r * KP + kkp + tg + 4];
            }
#pragma unroll
            for (int mt = 0; mt < MT; mt++)
#pragma unroll
                for (int nt = 0; nt < NTL; nt++) {
                    mma16816(acc[mt][nt], ah[mt], bh[nt]);
                    mma16816(acc[mt][nt], ah[mt], bl[nt]);
                    mma16816(acc[mt][nt], al[mt], bh[nt]);
                }
        }
        __syncthreads();
    }

    // ---- epilogue ----
#pragma unroll
    for (int mt = 0; mt < MT; mt++) {
#pragma unroll
        for (int nt = 0; nt < NTL; nt++) {
            int r0 = bm + wm + mt * 16 + g;
            int r1 = r0 + 8;
            int c0 = bn + wn + nt * 8 + 2 * tg;
            float v00 = acc[mt][nt][0], v01 = acc[mt][nt][1];
            float v10 = acc[mt][nt][2], v11 = acc[mt][nt][3];
            if (CI == 1) { v00 += Ci[c0]; v01 += Ci[c0 + 1]; v10 += Ci[c0]; v11 += Ci[c0 + 1]; }
            else if (CI == 2) {
                float2 t0 = *(const float2*)&Ci[(size_t)r0 * ldci + c0];
                float2 t1 = *(const float2*)&Ci[(size_t)r1 * ldci + c0];
                v00 += t0.x; v01 += t0.y; v10 += t1.x; v11 += t1.y;
            }
            if (RELU) {
                v00 = fmaxf(v00, 0.f); v01 = fmaxf(v01, 0.f);
                v10 = fmaxf(v10, 0.f); v11 = fmaxf(v11, 0.f);
            }
            *(float2*)&C[(size_t)r0 * ldc + c0] = make_float2(v00, v01);
            *(float2*)&C[(size_t)r1 * ldc + c0] = make_float2(v10, v11);
        }
    }
}

// ---------------- weight prep: split + transpose to bf16 hi/lo ----------------
__global__ void prep_bf16(const float* __restrict__ Wx, const float* __restrict__ Wh,
                          const float* __restrict__ W1, const float* __restrict__ W2,
                          const float* __restrict__ W3, const float* __restrict__ W4,
                          const float* __restrict__ W7)
{
    const size_t SA = (size_t)Gd * INd;      // WcatT
    const size_t SB = (size_t)Gd * Hd;       // WxhT
    const size_t SC = (size_t)Fd * Hd;       // W1T
    const size_t SD = (size_t)Fd * Fd;       // W2T
    const size_t SE = (size_t)Fd * Fd;       // W3T
    const size_t SF = (size_t)Zd * 1024;     // W4T
    const size_t SG = (size_t)Zd * 768;      // W7T
    const size_t SH = (size_t)Zd * Hd;       // W4bT
    const size_t SI = (size_t)Zd * Hd;       // W7bT
    size_t i = (size_t)blockIdx.x * blockDim.x + threadIdx.x;
    float v; __nv_bfloat16 h, l;

    if (i < SA) {
        int n = (int)(i % Gd), k = (int)(i / Gd);
        if (k < 64)       v = Wx[(size_t)k * Gd + n];
        else if (k < 320) v = Wx[(size_t)(512 + k) * Gd + n];
        else              v = Wh[(size_t)(k - 320) * Gd + n];
        bsplit(v, h, l);
        g_WcatT_h[(size_t)n * INd + k] = h; g_WcatT_l[(size_t)n * INd + k] = l;
        return;
    }
    i -= SA;
    if (i < SB) {
        int n = (int)(i % Gd), k = (int)(i / Gd);
        v = Wx[(size_t)(64 + k) * Gd + n];
        bsplit(v, h, l);
        g_WxhT_h[(size_t)n * Hd + k] = h; g_WxhT_l[(size_t)n * Hd + k] = l;
        return;
    }
    i -= SB;
    if (i < SC) {
        int n = (int)(i % Fd), k = (int)(i / Fd);
        bsplit(W1[(size_t)k * Fd + n], h, l);
        g_W1T_h[n * Hd + k] = h; g_W1T_l[n * Hd + k] = l;
        return;
    }
    i -= SC;
    if (i < SD) {
        int n = (int)(i % Fd), k = (int)(i / Fd);
        bsplit(W2[(size_t)k * Fd + n], h, l);
        g_W2T_h[n * Fd + k] = h; g_W2T_l[n * Fd + k] = l;
        return;
    }
    i -= SD;
    if (i < SE) {
        int n = (int)(i % Fd), k = (int)(i / Fd);
        bsplit(W3[(size_t)k * Fd + n], h, l);
        g_W3T_h[n * Fd + k] = h; g_W3T_l[n * Fd + k] = l;
        return;
    }
    i -= SE;
    if (i < SF) {
        int n = (int)(i % Zd), k = (int)(i / Zd);
        bsplit(W4[(size_t)(512 + k) * Zd + n], h, l);   // rows 512..1535 = [s|y_j|y_prev]
        g_W4T_h[n * 1024 + k] = h; g_W4T_l[n * 1024 + k] = l;
        return;
    }
    i -= SF;
    if (i < SG) {
        int n = (int)(i % Zd), k = (int)(i / Zd);
        bsplit(W7[(size_t)(512 + k) * Zd + n], h, l);   // rows 512..1279 = [s|y_prev]
        g_W7T_h[n * 768 + k] = h; g_W7T_l[n * 768 + k] = l;
        return;
    }
    i -= SG;
    if (i < SH) {
        int n = (int)(i % Zd), k = (int)(i / Zd);
        bsplit(W4[(size_t)k * Zd + n], h, l);           // rows 0..511 (h_i part)
        g_W4bT_h[n * Hd + k] = h; g_W4bT_l[n * Hd + k] = l;
        return;
    }
    i -= SH;
    if (i < SI) {
        int n = (int)(i % Zd), k = (int)(i / Zd);
        bsplit(W7[(size_t)k * Zd + n], h, l);
        g_W7bT_h[n * Hd + k] = h; g_W7bT_l[n * Hd + k] = l;
    }
}

// ---------------- pointwise kernels ----------------
__global__ void zero_state() {
    size_t n = (size_t)Bn * XLD + (size_t)Bn * Hd;
    size_t i = (size_t)blockIdx.x * blockDim.x + threadIdx.x;
    if (i >= n) return;
    if (i < (size_t)Bn * XLD) g_X[i] = 0.f;
    else g_c[i - (size_t)Bn * XLD] = 0.f;
}

__global__ void lstm_pw() {
    int idx = blockIdx.x * blockDim.x + threadIdx.x;
    if (idx >= Bn * Hd) return;
    int b = idx / Hd, j = idx % Hd;
    const float* gp = &g_gates[(size_t)b * Gd];
    float ig = gp[j], fg = gp[j + Hd], gg = gp[j + 2 * Hd], og = gp[j + 3 * Hd];
    float si = 1.f / (1.f + expf(-ig));
    float sf = 1.f / (1.f + expf(-fg));
    float so = 1.f / (1.f + expf(-og));
    float cn = sf * g_c[idx] + si * tanhf(gg);
    float hn = so * tanhf(cn);
    g_c[idx] = cn;
    g_X[(size_t)b * XLD + 320 + j] = hn;
}

__global__ void pack_pw(int t, float* __restrict__ out_fake) {
    int idx = blockIdx.x * blockDim.x + threadIdx.x;
    if (idx >= Bn * (Hd + Fd)) return;
    int b = idx / (Hd + Fd), c = idx % (Hd + Fd);
    if (c < Hd) {
        float v = g_c[b * Hd + c];
        g_infin[(size_t)b * 1024 + c] = v;
        g_priin[(size_t)b * 768 + c]  = v;
    } else {
        int f = c - Hd;
        float yv = g_y[b * Fd + f];
        float yp = g_X[(size_t)b * XLD + 64 + f];
        g_infin[(size_t)b * 1024 + 512 + f] = yv;
        g_infin[(size_t)b * 1024 + 768 + f] = yp;
        g_priin[(size_t)b * 768 + 512 + f]  = yp;
        g_X[(size_t)b * XLD + 64 + f] = yv;
        out_fake[(size_t)b * Td * Fd + (size_t)t * Fd + f] = yv;
    }
}

// fused K=64 head GEMMs + reparameterization (inference + prior)
__global__ void finish_both(int t,
    const float* __restrict__ W5, const float* __restrict__ b5,
    const float* __restrict__ W6, const float* __restrict__ b6,
    const float* __restrict__ W8, const float* __restrict__ b8,
    const float* __restrict__ W9, const float* __restrict__ b9,
    const float* __restrict__ eps_inf, const float* __restrict__ eps_pri,
    float* __restrict__ out_mean, float* __restrict__ out_lv, float* __restrict__ out_z)
{
    int idx = blockIdx.x * blockDim.x + threadIdx.x;
    if (idx >= Bn * Zd) return;
    int b = idx / Zd, z = idx % Zd;
    float m = b5[z], l = b6[z], mp = b8[z], lp = b9[z];
    const float* hz  = &g_hz [b * Zd];
    const float* hzp = &g_hzp[b * Zd];
#pragma unroll 8
    for (int k = 0; k < Zd; k++) {
        float a = hz[k], ap = hzp[k];
        m  += a  * W5[k * Zd + z];
        l  += a  * W6[k * Zd + z];
        mp += ap * W8[k * Zd + z];
        lp += ap * W9[k * Zd + z];
    }
    m = fmaxf(m, 0.f); l = fmaxf(l, 0.f); mp = fmaxf(mp, 0.f); lp = fmaxf(lp, 0.f);
    float zi = m  + eps_inf[(size_t)t * Bn * Zd + idx] * sqrtf(expf(l));
    float zp = mp + eps_pri[(size_t)t * Bn * Zd + idx] * sqrtf(expf(lp));
    out_mean[(size_t)b * Td * Zd + (size_t)t * Zd + z] = m;
    out_lv  [(size_t)b * Td * Zd + (size_t)t * Zd + z] = l;
    out_z[(size_t)(2 * t)     * Bn * Zd + idx] = zi;
    out_z[(size_t)(2 * t + 1) * Bn * Zd + idx] = zp;
    g_X[(size_t)b * XLD + z] = zi;
}

// ---------------- host ----------------
template<typename T> static T* sym(const void* s) { void* p = nullptr; cudaGetSymbolAddress(&p, s); return (T*)p; }

extern "C" void kernel_launch(void* const* d_in, const int* in_sizes, int n_in,
                              void* d_out, int out_size) {
    const float* h_i     = (const float*)d_in[0];
    const float* eps_inf = (const float*)d_in[1];
    const float* eps_pri = (const float*)d_in[2];
    const float* Wx      = (const float*)d_in[3];
    const float* Wh      = (const float*)d_in[4];
    const float* b_lstm  = (const float*)d_in[5];
    const float* W1 = (const float*)d_in[6],  *b1 = (const float*)d_in[7];
    const float* W2 = (const float*)d_in[8],  *b2 = (const float*)d_in[9];
    const float* W3 = (const float*)d_in[10], *b3 = (const float*)d_in[11];
    const float* W4 = (const float*)d_in[12], *b4 = (const float*)d_in[13];
    const float* W5 = (const float*)d_in[14], *b5 = (const float*)d_in[15];
    const float* W6 = (const float*)d_in[16], *b6 = (const float*)d_in[17];
    const float* W7 = (const float*)d_in[18], *b7 = (const float*)d_in[19];
    const float* W8 = (const float*)d_in[20], *b8 = (const float*)d_in[21];
    const float* W9 = (const float*)d_in[22], *b9 = (const float*)d_in[23];

    float* out      = (float*)d_out;
    float* out_fake = out;
    float* out_mean = out_fake + (size_t)Bn * Td * Fd;
    float* out_lv   = out_mean + (size_t)Bn * Td * Zd;
    float* out_z    = out_lv   + (size_t)Bn * Td * Zd;

    float* pBaseg = sym<float>(g_baseg); float* pBase4 = sym<float>(g_base4); float* pBase7 = sym<float>(g_base7);
    float* pGates = sym<float>(g_gates); float* pX = sym<float>(g_X);
    float* pY = sym<float>(g_y); float* pT1 = sym<float>(g_t1); float* pT2 = sym<float>(g_t2);
    float* pInf = sym<float>(g_infin); float* pPri = sym<float>(g_priin);
    float* pHz = sym<float>(g_hz); float* pHzp = sym<float>(g_hzp);

    __nv_bfloat16* WcatT_h = sym<__nv_bfloat16>(g_WcatT_h); __nv_bfloat16* WcatT_l = sym<__nv_bfloat16>(g_WcatT_l);
    __nv_bfloat16* WxhT_h  = sym<__nv_bfloat16>(g_WxhT_h);  __nv_bfloat16* WxhT_l  = sym<__nv_bfloat16>(g_WxhT_l);
    __nv_bfloat16* W1T_h   = sym<__nv_bfloat16>(g_W1T_h);   __nv_bfloat16* W1T_l   = sym<__nv_bfloat16>(g_W1T_l);
    __nv_bfloat16* W2T_h   = sym<__nv_bfloat16>(g_W2T_h);   __nv_bfloat16* W2T_l   = sym<__nv_bfloat16>(g_W2T_l);
    __nv_bfloat16* W3T_h   = sym<__nv_bfloat16>(g_W3T_h);   __nv_bfloat16* W3T_l   = sym<__nv_bfloat16>(g_W3T_l);
    __nv_bfloat16* W4T_h   = sym<__nv_bfloat16>(g_W4T_h);   __nv_bfloat16* W4T_l   = sym<__nv_bfloat16>(g_W4T_l);
    __nv_bfloat16* W7T_h   = sym<__nv_bfloat16>(g_W7T_h);   __nv_bfloat16* W7T_l   = sym<__nv_bfloat16>(g_W7T_l);
    __nv_bfloat16* W4bT_h  = sym<__nv_bfloat16>(g_W4bT_h);  __nv_bfloat16* W4bT_l  = sym<__nv_bfloat16>(g_W4bT_l);
    __nv_bfloat16* W7bT_h  = sym<__nv_bfloat16>(g_W7bT_h);  __nv_bfloat16* W7bT_l  = sym<__nv_bfloat16>(g_W7bT_l);

    {
        size_t n = (size_t)Bn * XLD + (size_t)Bn * Hd;
        zero_state<<<(unsigned)((n + 255) / 256), 256>>>();
        size_t tot = (size_t)Gd * INd + (size_t)Gd * Hd + (size_t)Fd * Hd
                   + 2 * (size_t)Fd * Fd + (size_t)Zd * 1024 + (size_t)Zd * 768
                   + 2 * (size_t)Zd * Hd;
        prep_bf16<<<(unsigned)((tot + 255) / 256), 256>>>(Wx, Wh, W1, W2, W3, W4, W7);
    }

    // hoisted base GEMMs (tensor core)
    mmagemm<128,128,64,32,256,false,1><<<dim3(Gd/128, Bn/128), 256>>>(
        h_i, Hd, WxhT_h, WxhT_l, b_lstm, 0, pBaseg, Gd, Hd);
    mmagemm<32,64,16,32,128,false,1><<<dim3(1, Bn/32), 128>>>(
        h_i, Hd, W4bT_h, W4bT_l, b4, 0, pBase4, Zd, Hd);
    mmagemm<32,64,16,32,128,false,1><<<dim3(1, Bn/32), 128>>>(
        h_i, Hd, W7bT_h, W7bT_l, b7, 0, pBase7, Zd, Hd);

    for (int t = 0; t < Td; t++) {
        // gates = base_g + [z|y_prev|h] @ Wcat^T   (M=4096,N=2048,K=832)
        mmagemm<128,128,64,32,256,false,2><<<dim3(Gd/128, Bn/128), 256>>>(
            pX, XLD, WcatT_h, WcatT_l, pBaseg, Gd, pGates, Gd, INd);
        lstm_pw<<<(Bn * Hd + 255) / 256, 256>>>();

        // decoder MLP
        mmagemm<64,64,32,32,128,true,1><<<dim3(Fd/64, Bn/64), 128>>>(
            pX + 320, XLD, W1T_h, W1T_l, b1, 0, pT1, Fd, Hd);
        mmagemm<64,64,32,32,128,true,1><<<dim3(Fd/64, Bn/64), 128>>>(
            pT1, Fd, W2T_h, W2T_l, b2, 0, pT2, Fd, Fd);
        mmagemm<64,64,32,32,128,true,1><<<dim3(Fd/64, Bn/64), 128>>>(
            pT2, Fd, W3T_h, W3T_l, b3, 0, pY, Fd, Fd);

        pack_pw<<<(Bn * (Hd + Fd) + 255) / 256, 256>>>(t, out_fake);

        // head first layers (K=1024 / K=768)
        mmagemm<32,64,16,32,128,true,2><<<dim3(1, Bn/32), 128>>>(
            pInf, 1024, W4T_h, W4T_l, pBase4, Zd, pHz, Zd, 1024);
        mmagemm<32,64,16,32,128,true,2><<<dim3(1, Bn/32), 128>>>(
            pPri, 768, W7T_h, W7T_l, pBase7, Zd, pHzp, Zd, 768);

        finish_both<<<(Bn * Zd + 255) / 256, 256>>>(t, W5, b5, W6, b6, W8, b8, W9, b9,
                                                    eps_inf, eps_pri, out_mean, out_lv, out_z);
    }
}

// round 4
// speedup vs baseline: 1.8931x; 1.2271x over previous
#include <cuda_runtime.h>
#include <cuda_bf16.h>
#include <math.h>
#include <stdint.h>

#define Bn   4096
#define Hd   512
#define Fd   256
#define Zd   64
#define Td   16
#define Gd   2048
#define XK   832      // bf16 X row: [z(64) | y(256) | h(512)]
#define IK   1024     // infA row:   [c(512) | y_j(256) | y_prev(256)]

// ---------------- persistent buffers ----------------
__device__ float g_baseg [(size_t)Bn * Gd];    // permuted layout
__device__ float g_basehz[Bn * 128];           // [base4 | base7]
__device__ float g_hzc   [Bn * 128];           // [hz | hzp]
__device__ float g_c     [Bn * Hd];
__device__ float g_blstmp[Gd];
__device__ float g_bhz   [128];

// double-buffered state X (read buf t&1, write buf (t+1)&1)
__device__ __nv_bfloat16 g_Xh0[(size_t)Bn * XK], g_Xl0[(size_t)Bn * XK];
__device__ __nv_bfloat16 g_Xh1[(size_t)Bn * XK], g_Xl1[(size_t)Bn * XK];
__device__ __nv_bfloat16 g_Ih [(size_t)Bn * IK], g_Il [(size_t)Bn * IK];
__device__ __nv_bfloat16 g_t1h[Bn * Fd], g_t1l[Bn * Fd];
__device__ __nv_bfloat16 g_t2h[Bn * Fd], g_t2l[Bn * Fd];
__device__ __nv_bfloat16 g_hih[(size_t)Bn * Hd], g_hil[(size_t)Bn * Hd];

// weights: n-major [N][K] bf16 hi/lo
__device__ __nv_bfloat16 g_WcatT_h[(size_t)Gd * XK], g_WcatT_l[(size_t)Gd * XK];
__device__ __nv_bfloat16 g_WxhT_h [(size_t)Gd * Hd], g_WxhT_l [(size_t)Gd * Hd];
__device__ __nv_bfloat16 g_W1T_h  [Fd * Hd], g_W1T_l  [Fd * Hd];
__device__ __nv_bfloat16 g_W2T_h  [Fd * Fd], g_W2T_l  [Fd * Fd];
__device__ __nv_bfloat16 g_W3T_h  [Fd * Fd], g_W3T_l  [Fd * Fd];
__device__ __nv_bfloat16 g_WheadT_h[128 * IK], g_WheadT_l[128 * IK];
__device__ __nv_bfloat16 g_WbaseT_h[128 * Hd], g_WbaseT_l[128 * Hd];

// ---------------- helpers ----------------
__device__ __forceinline__ void bsplit(float v, __nv_bfloat16& h, __nv_bfloat16& l) {
    h = __float2bfloat16_rn(v);
    l = __float2bfloat16_rn(v - __bfloat162float(h));
}
__device__ __forceinline__ __nv_bfloat162 bmk2(__nv_bfloat16 a, __nv_bfloat16 b) {
    __nv_bfloat162 t; t.x = a; t.y = b; return t;
}
__device__ __forceinline__ void mma16816(float* c, const uint32_t* a, const uint32_t* b) {
    asm volatile(
        "mma.sync.aligned.m16n8k16.row.col.f32.bf16.bf16.f32 "
        "{%0,%1,%2,%3}, {%4,%5,%6,%7}, {%8,%9}, {%0,%1,%2,%3};\n"
        : "+f"(c[0]), "+f"(c[1]), "+f"(c[2]), "+f"(c[3])
        : "r"(a[0]), "r"(a[1]), "r"(a[2]), "r"(a[3]), "r"(b[0]), "r"(b[1]));
}
__device__ __forceinline__ void cpa16(void* dst, const void* src) {
    uint32_t d = (uint32_t)__cvta_generic_to_shared(dst);
    asm volatile("cp.async.cg.shared.global [%0], [%1], 16;\n" :: "r"(d), "l"(src));
}

struct GArgs {
    const __nv_bfloat16 *Ah, *Al; int lda;
    const __nv_bfloat16 *Bh, *Bl;           // [N][K]
    const float* Ci; int ldci;
    float* C; int ldc;
    int K;
    float* cst;
    __nv_bfloat16 *Xh, *Xl;                 // WRITE state buffer (next step)
    const __nv_bfloat16 *XhR, *XlR;         // READ state buffer (current step)
    __nv_bfloat16 *Ih, *Il;
    __nv_bfloat16 *Dh, *Dl; int ldd;
    float* fake; int t;
};

template<int BM,int BN,int NTH>
__device__ __forceinline__ void stage_load(char* base, int tid, int bm, int bn,
    const __nv_bfloat16* Ah, const __nv_bfloat16* Al, int lda,
    const __nv_bfloat16* Bh, const __nv_bfloat16* Bl, int K, int k0)
{
#pragma unroll
    for (int i = tid; i < BM * 4; i += NTH) {
        int row = i >> 2, c4 = (i & 3) * 16;
        size_t off = ((size_t)(bm + row) * lda + k0) * 2 + c4;
        cpa16(base + row * 80 + c4, (const char*)Ah + off);
        cpa16(base + BM * 80 + row * 80 + c4, (const char*)Al + off);
    }
#pragma unroll
    for (int i = tid; i < BN * 4; i += NTH) {
        int row = i >> 2, c4 = (i & 3) * 16;
        size_t off = ((size_t)(bn + row) * K + k0) * 2 + c4;
        cpa16(base + BM * 160 + row * 80 + c4, (const char*)Bh + off);
        cpa16(base + BM * 160 + BN * 80 + row * 80 + c4, (const char*)Bl + off);
    }
    asm volatile("cp.async.commit_group;\n");
}

template<int BM,int BN,int MT,int NTL>
__device__ __forceinline__ void stage_mma(const char* base, float* acc,
                                          int wm, int wn, int gq, int tg)
{
    const uint32_t* As_h = (const uint32_t*)base;
    const uint32_t* As_l = (const uint32_t*)(base + BM * 80);
    const uint32_t* Bs_h = (const uint32_t*)(base + BM * 160);
    const uint32_t* Bs_l = (const uint32_t*)(base + BM * 160 + BN * 80);
#pragma unroll
    for (int kk = 0; kk < 16; kk += 8) {
        uint32_t ah[MT][4], al[MT][4], bh[NTL][2], bl[NTL][2];
#pragma unroll
        for (int mt = 0; mt < MT; mt++) {
            int r = wm + mt * 16 + gq;
            ah[mt][0] = As_h[r * 20 + kk + tg];
            ah[mt][1] = As_h[(r + 8) * 20 + kk + tg];
            ah[mt][2] = As_h[r * 20 + kk + tg + 4];
            ah[mt][3] = As_h[(r + 8) * 20 + kk + tg + 4];
            al[mt][0] = As_l[r * 20 + kk + tg];
            al[mt][1] = As_l[(r + 8) * 20 + kk + tg];
            al[mt][2] = As_l[r * 20 + kk + tg + 4];
            al[mt][3] = As_l[(r + 8) * 20 + kk + tg + 4];
        }
#pragma unroll
        for (int nt = 0; nt < NTL; nt++) {
            int r = wn + nt * 8 + gq;
            bh[nt][0] = Bs_h[r * 20 + kk + tg];
            bh[nt][1] = Bs_h[r * 20 + kk + tg + 4];
            bl[nt][0] = Bs_l[r * 20 + kk + tg];
            bl[nt][1] = Bs_l[r * 20 + kk + tg + 4];
        }
#pragma unroll
        for (int mt = 0; mt < MT; mt++)
#pragma unroll
            for (int nt = 0; nt < NTL; nt++) {
                float* a = acc + (mt * NTL + nt) * 4;
                mma16816(a, ah[mt], bh[nt]);
                mma16816(a, ah[mt], bl[nt]);
                mma16816(a, al[mt], bh[nt]);
            }
    }
}

// EPI: 0=store fp32 C, 1=LSTM, 2=relu->bf16 split dst, 3=decoder-3 y epilogue
template<int BM,int BN,int WM,int WN,int NTH,int EPI,int CI,bool RELU>
__global__ void __launch_bounds__(NTH) gemm(GArgs g)
{
    extern __shared__ char sm[];
    constexpr int MT = WM / 16, NTL = WN / 8, NWN = BN / WN;
    constexpr int stageB = (BM + BN) * 160;
    const int tid = threadIdx.x, warp = tid >> 5, lane = tid & 31;
    const int gq = lane >> 2, tg = lane & 3;
    const int wm = (warp / NWN) * WM, wn = (warp % NWN) * WN;
    const int bm = blockIdx.y * BM, bn = blockIdx.x * BN;
    const int K = g.K;

    float acc[MT * NTL * 4];
#pragma unroll
    for (int i = 0; i < MT * NTL * 4; i++) acc[i] = 0.f;

    const int nk = K >> 5;
    stage_load<BM,BN,NTH>(sm, tid, bm, bn, g.Ah, g.Al, g.lda, g.Bh, g.Bl, K, 0);
    for (int kt = 0; kt < nk; kt++) {
        if (kt + 1 < nk) {
            stage_load<BM,BN,NTH>(sm + ((kt + 1) & 1) * stageB, tid, bm, bn,
                                  g.Ah, g.Al, g.lda, g.Bh, g.Bl, K, (kt + 1) << 5);
            asm volatile("cp.async.wait_group 1;\n");
        } else {
            asm volatile("cp.async.wait_group 0;\n");
        }
        __syncthreads();
        stage_mma<BM,BN,MT,NTL>(sm + (kt & 1) * stageB, acc, wm, wn, gq, tg);
        __syncthreads();
    }

    if (EPI == 1) {
        // stage fp32 tile (with CI added), then LSTM pointwise.
        // NOTE: writes go to the WRITE state buffer (g.Xh/g.Xl) which is
        // disjoint from the READ buffer this kernel's A-loads use.
        float* tile = (float*)sm;
#pragma unroll
        for (int mt = 0; mt < MT; mt++)
#pragma unroll
            for (int nt = 0; nt < NTL; nt++) {
                int r0 = wm + mt * 16 + gq, c0 = wn + nt * 8 + 2 * tg;
                float* a = acc + (mt * NTL + nt) * 4;
                float v00 = a[0], v01 = a[1], v10 = a[2], v11 = a[3];
                if (CI == 2) {
                    const float* ci0 = g.Ci + (size_t)(bm + r0) * g.ldci + bn + c0;
                    const float* ci1 = g.Ci + (size_t)(bm + r0 + 8) * g.ldci + bn + c0;
                    v00 += ci0[0]; v01 += ci0[1]; v10 += ci1[0]; v11 += ci1[1];
                }
                tile[r0 * BN + c0] = v00; tile[r0 * BN + c0 + 1] = v01;
                tile[(r0 + 8) * BN + c0] = v10; tile[(r0 + 8) * BN + c0 + 1] = v11;
            }
        __syncthreads();
        for (int idx = tid; idx < BM * 32; idx += NTH) {
            int row = idx >> 5, w = idx & 31;
            float ig = tile[row * BN + w];
            float fg = tile[row * BN + 32 + w];
            float gg = tile[row * BN + 64 + w];
            float og = tile[row * BN + 96 + w];
            int b = bm + row, j = blockIdx.x * 32 + w;
            float si = 1.f / (1.f + expf(-ig));
            float sf = 1.f / (1.f + expf(-fg));
            float so = 1.f / (1.f + expf(-og));
            float cn = sf * g.cst[b * Hd + j] + si * tanhf(gg);
            float hn = so * tanhf(cn);
            g.cst[b * Hd + j] = cn;
            __nv_bfloat16 hh, hl, ch, cl;
            bsplit(hn, hh, hl); bsplit(cn, ch, cl);
            g.Xh[(size_t)b * XK + 320 + j] = hh;
            g.Xl[(size_t)b * XK + 320 + j] = hl;
            g.Ih[(size_t)b * IK + j] = ch;
            g.Il[(size_t)b * IK + j] = cl;
        }
        return;
    }

    // fragment-wise epilogues
#pragma unroll
    for (int mt = 0; mt < MT; mt++)
#pragma unroll
        for (int nt = 0; nt < NTL; nt++) {
            float* a = acc + (mt * NTL + nt) * 4;
#pragma unroll
            for (int half = 0; half < 2; half++) {
                int r = bm + wm + mt * 16 + gq + half * 8;
                int c = bn + wn + nt * 8 + 2 * tg;
                float v0 = a[half * 2], v1 = a[half * 2 + 1];
                if (CI == 1) { v0 += g.Ci[c]; v1 += g.Ci[c + 1]; }
                else if (CI == 2) {
                    const float* ci = g.Ci + (size_t)r * g.ldci + c;
                    v0 += ci[0]; v1 += ci[1];
                }
                if (RELU) { v0 = fmaxf(v0, 0.f); v1 = fmaxf(v1, 0.f); }
                if (EPI == 0) {
                    *(float2*)&g.C[(size_t)r * g.ldc + c] = make_float2(v0, v1);
                } else if (EPI == 2) {
                    __nv_bfloat16 h0, l0, h1, l1;
                    bsplit(v0, h0, l0); bsplit(v1, h1, l1);
                    *(__nv_bfloat162*)&g.Dh[(size_t)r * g.ldd + c] = bmk2(h0, h1);
                    *(__nv_bfloat162*)&g.Dl[(size_t)r * g.ldd + c] = bmk2(l0, l1);
                } else if (EPI == 3) {
                    // y epilogue: out_fake; old y (READ buf) -> Ih y_prev;
                    // new y -> Ih y_j and WRITE buf y slot.
                    *(float2*)&g.fake[(size_t)r * (Td * Fd) + g.t * Fd + c] = make_float2(v0, v1);
                    __nv_bfloat162 oh = *(const __nv_bfloat162*)&g.XhR[(size_t)r * XK + 64 + c];
                    __nv_bfloat162 ol = *(const __nv_bfloat162*)&g.XlR[(size_t)r * XK + 64 + c];
                    *(__nv_bfloat162*)&g.Ih[(size_t)r * IK + 768 + c] = oh;
                    *(__nv_bfloat162*)&g.Il[(size_t)r * IK + 768 + c] = ol;
                    __nv_bfloat16 h0, l0, h1, l1;
                    bsplit(v0, h0, l0); bsplit(v1, h1, l1);
                    *(__nv_bfloat162*)&g.Ih[(size_t)r * IK + 512 + c] = bmk2(h0, h1);
                    *(__nv_bfloat162*)&g.Il[(size_t)r * IK + 512 + c] = bmk2(l0, l1);
                    *(__nv_bfloat162*)&g.Xh[(size_t)r * XK + 64 + c] = bmk2(h0, h1);
                    *(__nv_bfloat162*)&g.Xl[(size_t)r * XK + 64 + c] = bmk2(l0, l1);
                }
            }
        }
}

// ---------------- prep kernels ----------------
__device__ __forceinline__ int perm_n(int np) {   // permuted row -> original gate col
    int chunk = np >> 7, r = np & 127, gate = r >> 5, w = r & 31;
    return gate * 512 + chunk * 32 + w;
}

__global__ void prep_wcat(const float* __restrict__ Wx, const float* __restrict__ Wh) {
    size_t i = (size_t)blockIdx.x * blockDim.x + threadIdx.x;
    if (i >= (size_t)Gd * XK) return;
    int k = (int)(i % XK), np = (int)(i / XK);
    int n = perm_n(np);
    float v;
    if (k < 64)       v = Wx[(size_t)k * Gd + n];
    else if (k < 320) v = Wx[(size_t)(512 + k) * Gd + n];
    else              v = Wh[(size_t)(k - 320) * Gd + n];
    __nv_bfloat16 h, l; bsplit(v, h, l);
    g_WcatT_h[i] = h; g_WcatT_l[i] = l;
}

__global__ void prep_wxh(const float* __restrict__ Wx, const float* __restrict__ bl) {
    size_t i = (size_t)blockIdx.x * blockDim.x + threadIdx.x;
    if (i >= (size_t)Gd * Hd) return;
    int k = (int)(i % Hd), np = (int)(i / Hd);
    int n = perm_n(np);
    __nv_bfloat16 h, l; bsplit(Wx[(size_t)(64 + k) * Gd + n], h, l);
    g_WxhT_h[i] = h; g_WxhT_l[i] = l;
    if (k == 0) g_blstmp[np] = bl[n];
}

__global__ void prep_dec(const float* __restrict__ W1, const float* __restrict__ W2,
                         const float* __restrict__ W3) {
    size_t i = (size_t)blockIdx.x * blockDim.x + threadIdx.x;
    const size_t s1 = Fd * Hd, s2 = s1 + Fd * Fd, s3 = s2 + Fd * Fd;
    __nv_bfloat16 h, l;
    if (i < s1) {
        int k = (int)(i % Hd), n = (int)(i / Hd);
        bsplit(W1[(size_t)k * Fd + n], h, l);
        g_W1T_h[i] = h; g_W1T_l[i] = l;
    } else if (i < s2) {
        size_t j = i - s1; int k = (int)(j % Fd), n = (int)(j / Fd);
        bsplit(W2[(size_t)k * Fd + n], h, l);
        g_W2T_h[j] = h; g_W2T_l[j] = l;
    } else if (i < s3) {
        size_t j = i - s2; int k = (int)(j % Fd), n = (int)(j / Fd);
        bsplit(W3[(size_t)k * Fd + n], h, l);
        g_W3T_h[j] = h; g_W3T_l[j] = l;
    }
}

__global__ void prep_head(const float* __restrict__ W4, const float* __restrict__ W7,
                          const float* __restrict__ b4, const float* __restrict__ b7) {
    size_t i = (size_t)blockIdx.x * blockDim.x + threadIdx.x;
    const size_t s1 = 128 * IK, s2 = s1 + 128 * Hd;
    __nv_bfloat16 h, l;
    if (i < s1) {
        int k = (int)(i % IK), n = (int)(i / IK);
        float v;
        if (n < 64) v = W4[(size_t)(512 + k) * Zd + n];
        else {
            int n2 = n - 64;
            if (k < 512)      v = W7[(size_t)(512 + k) * Zd + n2];
            else if (k < 768) v = 0.f;
            else              v = W7[(size_t)(1024 + k - 768) * Zd + n2];
        }
        bsplit(v, h, l);
        g_WheadT_h[i] = h; g_WheadT_l[i] = l;
    } else if (i < s2) {
        size_t j = i - s1; int k = (int)(j % Hd), n = (int)(j / Hd);
        float v = (n < 64) ? W4[(size_t)k * Zd + n] : W7[(size_t)k * Zd + (n - 64)];
        bsplit(v, h, l);
        g_WbaseT_h[j] = h; g_WbaseT_l[j] = l;
        if (k == 0) g_bhz[n] = (n < 64) ? b4[n] : b7[n - 64];
    }
}

__global__ void prep_hi(const float* __restrict__ h_i) {
    size_t i = (size_t)blockIdx.x * blockDim.x + threadIdx.x;
    if (i >= (size_t)Bn * Hd) return;
    __nv_bfloat16 h, l; bsplit(h_i[i], h, l);
    g_hih[i] = h; g_hil[i] = l;
}

__global__ void zero_state() {
    size_t i = (size_t)blockIdx.x * blockDim.x + threadIdx.x;
    const size_t nx = (size_t)Bn * XK;
    if (i < nx) {
        __nv_bfloat16 z = __float2bfloat16(0.f);
        g_Xh0[i] = z; g_Xl0[i] = z; g_Xh1[i] = z; g_Xl1[i] = z;
        return;
    }
    i -= nx;
    if (i < (size_t)Bn * Hd) g_c[i] = 0.f;
}

// fused tail: z5/z6/z8/z9 GEMMs (K=64) + reparameterization + state update
__global__ void finish_both(int t,
    const float* __restrict__ W5, const float* __restrict__ b5,
    const float* __restrict__ W6, const float* __restrict__ b6,
    const float* __restrict__ W8, const float* __restrict__ b8,
    const float* __restrict__ W9, const float* __restrict__ b9,
    const float* __restrict__ eps_inf, const float* __restrict__ eps_pri,
    float* __restrict__ out_mean, float* __restrict__ out_lv, float* __restrict__ out_z,
    __nv_bfloat16* __restrict__ Xh, __nv_bfloat16* __restrict__ Xl)
{
    int idx = blockIdx.x * blockDim.x + threadIdx.x;
    if (idx >= Bn * Zd) return;
    int b = idx / Zd, z = idx % Zd;
    float m = b5[z], l = b6[z], mp = b8[z], lp = b9[z];
    const float* hz  = &g_hzc[b * 128];
    const float* hzp = hz + 64;
#pragma unroll 8
    for (int k = 0; k < Zd; k++) {
        float a = hz[k], ap = hzp[k];
        m  += a  * W5[k * Zd + z];
        l  += a  * W6[k * Zd + z];
        mp += ap * W8[k * Zd + z];
        lp += ap * W9[k * Zd + z];
    }
    m = fmaxf(m, 0.f); l = fmaxf(l, 0.f); mp = fmaxf(mp, 0.f); lp = fmaxf(lp, 0.f);
    float zi = m  + eps_inf[(size_t)t * Bn * Zd + idx] * sqrtf(expf(l));
    float zp = mp + eps_pri[(size_t)t * Bn * Zd + idx] * sqrtf(expf(lp));
    out_mean[(size_t)b * Td * Zd + (size_t)t * Zd + z] = m;
    out_lv  [(size_t)b * Td * Zd + (size_t)t * Zd + z] = l;
    out_z[(size_t)(2 * t)     * Bn * Zd + idx] = zi;
    out_z[(size_t)(2 * t + 1) * Bn * Zd + idx] = zp;
    __nv_bfloat16 zh, zl; bsplit(zi, zh, zl);
    Xh[(size_t)b * XK + z] = zh;
    Xl[(size_t)b * XK + z] = zl;
}

// ---------------- host ----------------
template<typename T> static T* sym(const void* s) { void* p = nullptr; cudaGetSymbolAddress(&p, s); return (T*)p; }

extern "C" void kernel_launch(void* const* d_in, const int* in_sizes, int n_in,
                              void* d_out, int out_size) {
    const float* h_i     = (const float*)d_in[0];
    const float* eps_inf = (const float*)d_in[1];
    const float* eps_pri = (const float*)d_in[2];
    const float* Wx      = (const float*)d_in[3];
    const float* Wh      = (const float*)d_in[4];
    const float* b_lstm  = (const float*)d_in[5];
    const float* W1 = (const float*)d_in[6],  *b1 = (const float*)d_in[7];
    const float* W2 = (const float*)d_in[8],  *b2 = (const float*)d_in[9];
    const float* W3 = (const float*)d_in[10], *b3 = (const float*)d_in[11];
    const float* W4 = (const float*)d_in[12], *b4 = (const float*)d_in[13];
    const float* W5 = (const float*)d_in[14], *b5 = (const float*)d_in[15];
    const float* W6 = (const float*)d_in[16], *b6 = (const float*)d_in[17];
    const float* W7 = (const float*)d_in[18], *b7 = (const float*)d_in[19];
    const float* W8 = (const float*)d_in[20], *b8 = (const float*)d_in[21];
    const float* W9 = (const float*)d_in[22], *b9 = (const float*)d_in[23];

    float* out      = (float*)d_out;
    float* out_fake = out;
    float* out_mean = out_fake + (size_t)Bn * Td * Fd;
    float* out_lv   = out_mean + (size_t)Bn * Td * Zd;
    float* out_z    = out_lv   + (size_t)Bn * Td * Zd;

    __nv_bfloat16* Xh0 = sym<__nv_bfloat16>(g_Xh0); __nv_bfloat16* Xl0 = sym<__nv_bfloat16>(g_Xl0);
    __nv_bfloat16* Xh1 = sym<__nv_bfloat16>(g_Xh1); __nv_bfloat16* Xl1 = sym<__nv_bfloat16>(g_Xl1);

    GArgs a{};
    a.cst = sym<float>(g_c);
    a.Ih = sym<__nv_bfloat16>(g_Ih); a.Il = sym<__nv_bfloat16>(g_Il);

    float* pBaseg  = sym<float>(g_baseg);
    float* pBasehz = sym<float>(g_basehz);
    float* pHzc    = sym<float>(g_hzc);
    float* pBlstmp = sym<float>(g_blstmp);
    float* pBhz    = sym<float>(g_bhz);

    constexpr int SM128128 = (128 + 128) * 160 * 2;   // 81920
    constexpr int SM12864  = (128 + 64) * 160 * 2;    // 61440
    constexpr int SM6464   = (64 + 64) * 160 * 2;     // 40960
    cudaFuncSetAttribute(gemm<128,128,64,32,256,0,1,false>, cudaFuncAttributeMaxDynamicSharedMemorySize, SM128128);
    cudaFuncSetAttribute(gemm<128,128,64,32,256,1,2,false>, cudaFuncAttributeMaxDynamicSharedMemorySize, SM128128);
    cudaFuncSetAttribute(gemm<128,64,64,32,128,2,1,true>,   cudaFuncAttributeMaxDynamicSharedMemorySize, SM12864);
    cudaFuncSetAttribute(gemm<128,64,64,32,128,3,1,true>,   cudaFuncAttributeMaxDynamicSharedMemorySize, SM12864);
    cudaFuncSetAttribute(gemm<64,64,32,32,128,0,2,true>,    cudaFuncAttributeMaxDynamicSharedMemorySize, SM6464);
    cudaFuncSetAttribute(gemm<64,64,32,32,128,0,1,false>,   cudaFuncAttributeMaxDynamicSharedMemorySize, SM6464);

    // ---- init ----
    {
        size_t n = (size_t)Bn * XK + (size_t)Bn * Hd;
        zero_state<<<(unsigned)((n + 255) / 256), 256>>>();
        prep_wcat<<<(unsigned)(((size_t)Gd * XK + 255) / 256), 256>>>(Wx, Wh);
        prep_wxh<<<(unsigned)(((size_t)Gd * Hd + 255) / 256), 256>>>(Wx, b_lstm);
        prep_dec<<<(unsigned)(((size_t)Fd * Hd + 2 * Fd * Fd + 255) / 256), 256>>>(W1, W2, W3);
        prep_head<<<(unsigned)((128 * (IK + Hd) + 255) / 256), 256>>>(W4, W7, b4, b7);
        prep_hi<<<(unsigned)(((size_t)Bn * Hd + 255) / 256), 256>>>(h_i);
    }

    // ---- hoisted base GEMMs ----
    {
        GArgs b = a;
        b.Ah = sym<__nv_bfloat16>(g_hih); b.Al = sym<__nv_bfloat16>(g_hil); b.lda = Hd;
        b.Bh = sym<__nv_bfloat16>(g_WxhT_h); b.Bl = sym<__nv_bfloat16>(g_WxhT_l);
        b.Ci = pBlstmp; b.C = pBaseg; b.ldc = Gd; b.K = Hd;
        gemm<128,128,64,32,256,0,1,false><<<dim3(16, 32), 256, SM128128>>>(b);

        b.Bh = sym<__nv_bfloat16>(g_WbaseT_h); b.Bl = sym<__nv_bfloat16>(g_WbaseT_l);
        b.Ci = pBhz; b.C = pBasehz; b.ldc = 128; b.K = Hd;
        gemm<64,64,32,32,128,0,1,false><<<dim3(2, 64), 128, SM6464>>>(b);
    }

    for (int t = 0; t < Td; t++) {
        __nv_bfloat16* XrH = (t & 1) ? Xh1 : Xh0;  // read buffer
        __nv_bfloat16* XrL = (t & 1) ? Xl1 : Xl0;
        __nv_bfloat16* XwH = (t & 1) ? Xh0 : Xh1;  // write buffer (next step)
        __nv_bfloat16* XwL = (t & 1) ? Xl0 : Xl1;

        // gate GEMM + fused LSTM  (M=4096,N=2048,K=832)  reads Xr, writes h -> Xw
        {
            GArgs b = a;
            b.Ah = XrH; b.Al = XrL; b.lda = XK;
            b.Bh = sym<__nv_bfloat16>(g_WcatT_h); b.Bl = sym<__nv_bfloat16>(g_WcatT_l);
            b.Ci = pBaseg; b.ldci = Gd; b.K = XK;
            b.Xh = XwH; b.Xl = XwL;
            gemm<128,128,64,32,256,1,2,256 ? false : false><<<dim3(16, 32), 256, SM128128>>>(b);
        }
        // decoder MLP (reads NEW h from write buffer — sequenced by kernel boundary)
        {
            GArgs b = a;
            b.Ah = XwH + 320; b.Al = XwL + 320; b.lda = XK;
            b.Bh = sym<__nv_bfloat16>(g_W1T_h); b.Bl = sym<__nv_bfloat16>(g_W1T_l);
            b.Ci = b1; b.K = Hd;
            b.Dh = sym<__nv_bfloat16>(g_t1h); b.Dl = sym<__nv_bfloat16>(g_t1l); b.ldd = Fd;
            gemm<128,64,64,32,128,2,1,true><<<dim3(4, 32), 128, SM12864>>>(b);

            b.Ah = sym<__nv_bfloat16>(g_t1h); b.Al = sym<__nv_bfloat16>(g_t1l); b.lda = Fd;
            b.Bh = sym<__nv_bfloat16>(g_W2T_h); b.Bl = sym<__nv_bfloat16>(g_W2T_l);
            b.Ci = b2; b.K = Fd;
            b.Dh = sym<__nv_bfloat16>(g_t2h); b.Dl = sym<__nv_bfloat16>(g_t2l);
            gemm<128,64,64,32,128,2,1,true><<<dim3(4, 32), 128, SM12864>>>(b);

            b.Ah = sym<__nv_bfloat16>(g_t2h); b.Al = sym<__nv_bfloat16>(g_t2l); b.lda = Fd;
            b.Bh = sym<__nv_bfloat16>(g_W3T_h); b.Bl = sym<__nv_bfloat16>(g_W3T_l);
            b.Ci = b3; b.K = Fd;
            b.fake = out_fake; b.t = t;
            b.XhR = XrH; b.XlR = XrL;       // old y source
            b.Xh  = XwH; b.Xl  = XwL;       // new y target
            gemm<128,64,64,32,128,3,1,true><<<dim3(4, 32), 128, SM12864>>>(b);
        }
        // merged heads: [hz|hzp] = relu(infA @ [W4|W7pad] + basehz)
        {
            GArgs b = a;
            b.Ah = a.Ih; b.Al = a.Il; b.lda = IK;
            b.Bh = sym<__nv_bfloat16>(g_WheadT_h); b.Bl = sym<__nv_bfloat16>(g_WheadT_l);
            b.Ci = pBasehz; b.ldci = 128; b.C = pHzc; b.ldc = 128; b.K = IK;
            gemm<64,64,32,32,128,0,2,true><<<dim3(2, 64), 128, SM6464>>>(b);
        }
        finish_both<<<(Bn * Zd + 255) / 256, 256>>>(t, W5, b5, W6, b6, W8, b8, W9, b9,
                                                    eps_inf, eps_pri, out_mean, out_lv, out_z,
                                                    XwH, XwL);
    }
}